// round 9
// baseline (speedup 1.0000x reference)
#include <cuda_runtime.h>
#include <cstdint>

// out[b,t,:] = [ features[b,t,:] @ W^T + bias , pe(positions[t]) ]
// B=16384, T=64, F=16, Dh=128. Output = 65536 contiguous 16KB "units".
//
// Round-8 structure, quartered CTAs: TPB=128, unit=16 rows, GRID=592
// -> 4 CTAs/SM = 4 independent TMA store streams per SM.

#define T_DIM 64
#define F_DIM 16
#define DH    128
#define GRID  592          // multiple of 4 -> unit (u mod 4) fixed per block
#define TPB   128
#define STG_FLOATS  4096   // 16 rows * 256 cols
#define FFB_FLOATS  256    // 16 rows * 16
#define SMEM_BYTES  (2 * STG_FLOATS * 4 + 2 * FFB_FLOATS * 4)   // 34816

__device__ __forceinline__ uint32_t smem_u32(const void* p)
{
    return (uint32_t)__cvta_generic_to_shared(p);
}
__device__ __forceinline__ void cp16(uint32_t dst, const void* src)
{
    asm volatile("cp.async.cg.shared.global [%0], [%1], 16;" :: "r"(dst), "l"(src));
}
__device__ __forceinline__ unsigned long long pack2(float a, float b)
{
    unsigned long long r;
    asm("mov.b64 %0, {%1, %2};" : "=l"(r) : "f"(a), "f"(b));
    return r;
}
__device__ __forceinline__ void fma2(unsigned long long& d,
                                     unsigned long long a, unsigned long long b)
{
    asm("fma.rn.f32x2 %0, %1, %2, %0;" : "+l"(d) : "l"(a), "l"(b));
}

__global__ __launch_bounds__(TPB, 4) void obs_embed_kernel(
    const float* __restrict__ features,   // [B,64,16]
    const float* __restrict__ W,          // [128,16]
    const float* __restrict__ bias,       // [128]
    const int*   __restrict__ positions,  // [64]
    float*       __restrict__ out,        // [B,64,256]
    int nUnits)                           // B*4
{
    extern __shared__ float smem[];
    float* stg0 = smem;                   // [16][256] staging, buffer 0
    float* stg1 = smem + STG_FLOATS;      // buffer 1
    float* ffb  = smem + 2 * STG_FLOATS;  // [2][16][16] feature staging

    const int tid  = threadIdx.x;
    const int lane = tid & 31;
    const int warp = tid >> 5;

    const int t0 = (blockIdx.x & 3) * 16;    // unit quarter fixed (GRID%4==0)

    int u = blockIdx.x;

    // Prologue FIRST: prefetch unit u features (overlaps pe compute below).
    // Warp w owns rows 4w..4w+3: 256B = 16 lanes x 16B.
    if (u < nUnits && lane < 16)
        cp16(smem_u32(ffb + warp * 64 + lane * 4),
             features + (size_t)u * 256 + warp * 64 + lane * 4);
    asm volatile("cp.async.commit_group;");

    // pe halves of both staging buffers: constant for this block.
    // All-float: exp2f (MUFU) + sincosf (proven rel_err ~1.1e-6 in round 8).
    for (int idx = tid; idx < 16 * 64; idx += TPB) {
        int r = idx >> 6, j = idx & 63;
        float pos  = (float)__ldg(positions + t0 + r);
        float invf = exp2f((float)j * (-13.287712379549449f / 32.0f));
        float s, c;
        sincosf(pos * invf, &s, &c);
        stg0[r * 256 + DH + 2 * j]     = s;
        stg0[r * 256 + DH + 2 * j + 1] = c;
        stg1[r * 256 + DH + 2 * j]     = s;
        stg1[r * 256 + DH + 2 * j + 1] = c;
    }

    // W into packed registers. Lane owns output cols d = 4*lane + {0..3}.
    unsigned long long wp0[16], wp1[16];
    {
        const float4* Wv = reinterpret_cast<const float4*>(W);
        #pragma unroll
        for (int q = 0; q < 4; ++q) {
            float4 w0 = __ldg(Wv + (4 * lane + 0) * 4 + q);
            float4 w1 = __ldg(Wv + (4 * lane + 1) * 4 + q);
            float4 w2 = __ldg(Wv + (4 * lane + 2) * 4 + q);
            float4 w3 = __ldg(Wv + (4 * lane + 3) * 4 + q);
            wp0[4*q+0] = pack2(w0.x, w1.x);  wp1[4*q+0] = pack2(w2.x, w3.x);
            wp0[4*q+1] = pack2(w0.y, w1.y);  wp1[4*q+1] = pack2(w2.y, w3.y);
            wp0[4*q+2] = pack2(w0.z, w1.z);  wp1[4*q+2] = pack2(w2.z, w3.z);
            wp0[4*q+3] = pack2(w0.w, w1.w);  wp1[4*q+3] = pack2(w2.w, w3.w);
        }
    }
    const unsigned long long bp0 = pack2(__ldg(bias + 4 * lane + 0),
                                         __ldg(bias + 4 * lane + 1));
    const unsigned long long bp1 = pack2(__ldg(bias + 4 * lane + 2),
                                         __ldg(bias + 4 * lane + 3));

    int p = 0;
    for (; u < nUnits; u += GRID, p ^= 1) {
        // Prefetch next unit's features into the other buffer.
        {
            int un = u + GRID;
            if (un < nUnits && lane < 16)
                cp16(smem_u32(ffb + (p ^ 1) * FFB_FLOATS + warp * 64 + lane * 4),
                     features + (size_t)un * 256 + warp * 64 + lane * 4);
            asm volatile("cp.async.commit_group;");
        }

        // Reuse gate: TMA smem-read of buffer p (issued 2 iters ago) done.
        if (tid == 0) asm volatile("cp.async.bulk.wait_group.read 1;");
        __syncthreads();

        // Current features (committed last iter / prologue) ready.
        asm volatile("cp.async.wait_group 1;");
        __syncwarp();

        float* stgp = p ? stg1 : stg0;
        const float* fcur = ffb + p * FFB_FLOATS + warp * 64;   // warp's 4 rows

        #pragma unroll
        for (int rr = 0; rr < 4; ++rr) {
            const float4* frow = reinterpret_cast<const float4*>(fcur + rr * 16);
            unsigned long long a0 = bp0, a1 = bp1;
            #pragma unroll
            for (int q = 0; q < 4; ++q) {
                const float4 f = frow[q];   // broadcast LDS, conflict-free
                unsigned long long ff;
                ff = pack2(f.x, f.x); fma2(a0, ff, wp0[4*q+0]); fma2(a1, ff, wp1[4*q+0]);
                ff = pack2(f.y, f.y); fma2(a0, ff, wp0[4*q+1]); fma2(a1, ff, wp1[4*q+1]);
                ff = pack2(f.z, f.z); fma2(a0, ff, wp0[4*q+2]); fma2(a1, ff, wp1[4*q+2]);
                ff = pack2(f.w, f.w); fma2(a0, ff, wp0[4*q+3]); fma2(a1, ff, wp1[4*q+3]);
            }
            uint32_t sa = smem_u32(stgp + (warp * 4 + rr) * 256 + lane * 4);
            asm volatile("st.shared.v2.u64 [%0], {%1, %2};"
                         :: "r"(sa), "l"(a0), "l"(a1));
        }
        __syncthreads();

        if (tid == 0) {
            asm volatile("fence.proxy.async.shared::cta;");
            asm volatile(
                "cp.async.bulk.global.shared::cta.bulk_group [%0], [%1], %2;"
                :: "l"(out + (size_t)u * STG_FLOATS),
                   "r"(smem_u32(stgp)), "r"(16384) : "memory");
            asm volatile("cp.async.bulk.commit_group;");
        }
    }
    // Drain outstanding bulk stores before CTA exit (smem must stay live).
    asm volatile("cp.async.bulk.wait_group 0;");
    __syncthreads();
}

extern "C" void kernel_launch(void* const* d_in, const int* in_sizes, int n_in,
                              void* d_out, int out_size)
{
    const float* features  = (const float*)d_in[0];
    const float* W         = (const float*)d_in[1];
    const float* bias      = (const float*)d_in[2];
    const int*   positions = (const int*)d_in[3];
    float* out = (float*)d_out;

    const int B = in_sizes[0] / (T_DIM * F_DIM);

    cudaFuncSetAttribute(obs_embed_kernel,
                         cudaFuncAttributeMaxDynamicSharedMemorySize, SMEM_BYTES);

    obs_embed_kernel<<<GRID, TPB, SMEM_BYTES>>>(features, W, bias, positions,
                                                out, B * 4);
}

// round 10
// speedup vs baseline: 1.2033x; 1.2033x over previous
#include <cuda_runtime.h>
#include <cuda.h>
#include <cstdint>

// out[b,t,:] = [ features[b,t,:] @ W^T + bias , pe(positions[t]) ]
// B=16384, T=64, F=16, Dh=128. Output rows of 256 floats; unit = 32 rows.
//
// Round-8 loop, but the 32KB unit is written by TWO 2D TMA tensor stores
// (column tiles, 1KB pitch): feature half from a 16KB double-buffered
// staging tile, pe half from a CONSTANT 16KB buffer written once per block.
// Halves per-iteration STS/smem traffic vs round 8.

#define T_DIM 64
#define F_DIM 16
#define DH    128
#define GRID  296          // even -> unit parity fixed per block
#define TPB   256
#define FSTG_FLOATS 4096   // 32 rows * 128 cols (feature half)
#define PE_FLOATS   4096   // 32 rows * 128 cols (pe half, constant)
#define FFB_FLOATS  512    // 32 rows * 16
#define SMEM_BYTES  ((2 * FSTG_FLOATS + PE_FLOATS + 2 * FFB_FLOATS) * 4)  // 53248

__device__ __forceinline__ uint32_t smem_u32(const void* p)
{
    return (uint32_t)__cvta_generic_to_shared(p);
}
__device__ __forceinline__ void cp16(uint32_t dst, const void* src)
{
    asm volatile("cp.async.cg.shared.global [%0], [%1], 16;" :: "r"(dst), "l"(src));
}
__device__ __forceinline__ unsigned long long pack2(float a, float b)
{
    unsigned long long r;
    asm("mov.b64 %0, {%1, %2};" : "=l"(r) : "f"(a), "f"(b));
    return r;
}
__device__ __forceinline__ void fma2(unsigned long long& d,
                                     unsigned long long a, unsigned long long b)
{
    asm("fma.rn.f32x2 %0, %1, %2, %0;" : "+l"(d) : "l"(a), "l"(b));
}

__global__ __launch_bounds__(TPB, 2) void obs_embed_kernel(
    const float* __restrict__ features,   // [B,64,16]
    const float* __restrict__ W,          // [128,16]
    const float* __restrict__ bias,       // [128]
    const int*   __restrict__ positions,  // [64]
    const __grid_constant__ CUtensorMap mapF,   // feature half (cols 0..127)
    const __grid_constant__ CUtensorMap mapP,   // pe half     (cols 128..255)
    int nUnits)                           // B*2
{
    extern __shared__ float smem[];
    float* fstg0 = smem;                        // [32][128] feature staging 0
    float* fstg1 = smem + FSTG_FLOATS;          // buffer 1
    float* pes   = smem + 2 * FSTG_FLOATS;      // [32][128] constant pe tile
    float* ffb   = smem + 2 * FSTG_FLOATS + PE_FLOATS;  // [2][32][16]

    const int tid  = threadIdx.x;
    const int lane = tid & 31;
    const int warp = tid >> 5;

    const int t0 = (blockIdx.x & 1) * 32;    // unit parity fixed (GRID even)

    int u = blockIdx.x;

    // Prologue FIRST: prefetch unit u features (overlaps pe compute below).
    if (u < nUnits && lane < 16)
        cp16(smem_u32(ffb + warp * 64 + lane * 4),
             features + (size_t)u * 512 + warp * 64 + lane * 4);
    asm volatile("cp.async.commit_group;");

    // Constant pe tile, written ONCE. All-float math (round-8 proven,
    // rel_err 1.1e-6): exp2f (MUFU) + sincosf.
    for (int idx = tid; idx < 32 * 64; idx += TPB) {
        int r = idx >> 6, j = idx & 63;
        float pos  = (float)__ldg(positions + t0 + r);
        float invf = exp2f((float)j * (-13.287712379549449f / 32.0f));
        float s, c;
        sincosf(pos * invf, &s, &c);
        pes[r * DH + 2 * j]     = s;
        pes[r * DH + 2 * j + 1] = c;
    }

    // W into packed registers. Lane owns output cols d = 4*lane + {0..3}.
    unsigned long long wp0[16], wp1[16];
    {
        const float4* Wv = reinterpret_cast<const float4*>(W);
        #pragma unroll
        for (int q = 0; q < 4; ++q) {
            float4 w0 = __ldg(Wv + (4 * lane + 0) * 4 + q);
            float4 w1 = __ldg(Wv + (4 * lane + 1) * 4 + q);
            float4 w2 = __ldg(Wv + (4 * lane + 2) * 4 + q);
            float4 w3 = __ldg(Wv + (4 * lane + 3) * 4 + q);
            wp0[4*q+0] = pack2(w0.x, w1.x);  wp1[4*q+0] = pack2(w2.x, w3.x);
            wp0[4*q+1] = pack2(w0.y, w1.y);  wp1[4*q+1] = pack2(w2.y, w3.y);
            wp0[4*q+2] = pack2(w0.z, w1.z);  wp1[4*q+2] = pack2(w2.z, w3.z);
            wp0[4*q+3] = pack2(w0.w, w1.w);  wp1[4*q+3] = pack2(w2.w, w3.w);
        }
    }
    const unsigned long long bp0 = pack2(__ldg(bias + 4 * lane + 0),
                                         __ldg(bias + 4 * lane + 1));
    const unsigned long long bp1 = pack2(__ldg(bias + 4 * lane + 2),
                                         __ldg(bias + 4 * lane + 3));

    int p = 0;
    for (; u < nUnits; u += GRID, p ^= 1) {
        // Prefetch next unit's features into the other buffer.
        {
            int un = u + GRID;
            if (un < nUnits && lane < 16)
                cp16(smem_u32(ffb + (p ^ 1) * FFB_FLOATS + warp * 64 + lane * 4),
                     features + (size_t)un * 512 + warp * 64 + lane * 4);
            asm volatile("cp.async.commit_group;");
        }

        // Reuse gate: TMA smem-read of fstg[p] (issued 2 iters ago) done.
        if (tid == 0) asm volatile("cp.async.bulk.wait_group.read 1;");
        __syncthreads();

        // Current features (committed last iter / prologue) ready.
        asm volatile("cp.async.wait_group 1;");
        __syncwarp();

        float* stgp = p ? fstg1 : fstg0;
        const float* fcur = ffb + p * FFB_FLOATS + warp * 64;  // warp's 4 rows

        #pragma unroll
        for (int rr = 0; rr < 4; ++rr) {
            const float4* frow = reinterpret_cast<const float4*>(fcur + rr * 16);
            unsigned long long a0 = bp0, a1 = bp1;
            #pragma unroll
            for (int q = 0; q < 4; ++q) {
                const float4 f = frow[q];   // broadcast LDS, conflict-free
                unsigned long long ff;
                ff = pack2(f.x, f.x); fma2(a0, ff, wp0[4*q+0]); fma2(a1, ff, wp1[4*q+0]);
                ff = pack2(f.y, f.y); fma2(a0, ff, wp0[4*q+1]); fma2(a1, ff, wp1[4*q+1]);
                ff = pack2(f.z, f.z); fma2(a0, ff, wp0[4*q+2]); fma2(a1, ff, wp1[4*q+2]);
                ff = pack2(f.w, f.w); fma2(a0, ff, wp0[4*q+3]); fma2(a1, ff, wp1[4*q+3]);
            }
            // Feature half only: row stride 128 floats.
            uint32_t sa = smem_u32(stgp + (warp * 4 + rr) * DH + lane * 4);
            asm volatile("st.shared.v2.u64 [%0], {%1, %2};"
                         :: "r"(sa), "l"(a0), "l"(a1));
        }
        __syncthreads();

        if (tid == 0) {
            const int row0 = u * 32;
            asm volatile("fence.proxy.async.shared::cta;");
            asm volatile(
                "cp.async.bulk.tensor.2d.global.shared::cta.tile.bulk_group "
                "[%0, {%1, %2}], [%3];"
                :: "l"(&mapF), "r"(0), "r"(row0), "r"(smem_u32(stgp)) : "memory");
            asm volatile(
                "cp.async.bulk.tensor.2d.global.shared::cta.tile.bulk_group "
                "[%0, {%1, %2}], [%3];"
                :: "l"(&mapP), "r"(0), "r"(row0), "r"(smem_u32(pes)) : "memory");
            asm volatile("cp.async.bulk.commit_group;");
        }
    }
    // Drain outstanding bulk stores before CTA exit (smem must stay live).
    asm volatile("cp.async.bulk.wait_group 0;");
    __syncthreads();
}

extern "C" void kernel_launch(void* const* d_in, const int* in_sizes, int n_in,
                              void* d_out, int out_size)
{
    const float* features  = (const float*)d_in[0];
    const float* W         = (const float*)d_in[1];
    const float* bias      = (const float*)d_in[2];
    const int*   positions = (const int*)d_in[3];
    float* out = (float*)d_out;

    const int B = in_sizes[0] / (T_DIM * F_DIM);
    const int nUnits = B * 2;
    const unsigned long long nRows = (unsigned long long)nUnits * 32;

    // cuTensorMapEncodeTiled via cudart entry-point lookup (no -lcuda needed).
    typedef CUresult (*EncodeFn)(
        CUtensorMap*, CUtensorMapDataType, cuuint32_t, void*,
        const cuuint64_t*, const cuuint64_t*, const cuuint32_t*,
        const cuuint32_t*, CUtensorMapInterleave, CUtensorMapSwizzle,
        CUtensorMapL2promotion, CUtensorMapFloatOOBfill);
    EncodeFn encode = nullptr;
    cudaDriverEntryPointQueryResult qres;
    cudaGetDriverEntryPoint("cuTensorMapEncodeTiled", (void**)&encode,
                            cudaEnableDefault, &qres);

    // Output viewed as [nRows, 256] f32, pitch 1024B. Two column tiles:
    // cols [0,128) (feature half) and [128,256) (pe half). Box [128, 32].
    cuuint64_t dims[2]    = {128, nRows};
    cuuint64_t strides[1] = {1024};
    cuuint32_t box[2]     = {128, 32};
    cuuint32_t estr[2]    = {1, 1};

    CUtensorMap mapF, mapP;
    encode(&mapF, CU_TENSOR_MAP_DATA_TYPE_FLOAT32, 2, (void*)out,
           dims, strides, box, estr,
           CU_TENSOR_MAP_INTERLEAVE_NONE, CU_TENSOR_MAP_SWIZZLE_NONE,
           CU_TENSOR_MAP_L2_PROMOTION_L2_128B, CU_TENSOR_MAP_FLOAT_OOB_FILL_NONE);
    encode(&mapP, CU_TENSOR_MAP_DATA_TYPE_FLOAT32, 2, (void*)(out + DH),
           dims, strides, box, estr,
           CU_TENSOR_MAP_INTERLEAVE_NONE, CU_TENSOR_MAP_SWIZZLE_NONE,
           CU_TENSOR_MAP_L2_PROMOTION_L2_128B, CU_TENSOR_MAP_FLOAT_OOB_FILL_NONE);

    cudaFuncSetAttribute(obs_embed_kernel,
                         cudaFuncAttributeMaxDynamicSharedMemorySize, SMEM_BYTES);

    obs_embed_kernel<<<GRID, TPB, SMEM_BYTES>>>(features, W, bias, positions,
                                                mapF, mapP, nUnits);
}

// round 11
// speedup vs baseline: 1.2183x; 1.0125x over previous
#include <cuda_runtime.h>
#include <cuda.h>
#include <cstdint>

// out[b,t,:] = [ features[b,t,:] @ W^T + bias , pe(positions[t]) ]
// B=16384, T=64, F=16, Dh=128.
//
// Unit = FULL batch row b: 64 rows = 64KB contiguous output. Round-10 loop
// (NBUF=2, 2D TMA column-tile stores, constant pe tile) with doubled unit
// size to halve per-byte pipeline overhead. Each warp computes 8 rows/iter.

#define T_DIM 64
#define F_DIM 16
#define DH    128
#define GRID  296
#define TPB   256
#define FSTG_FLOATS 8192   // 64 rows * 128 cols (feature half)
#define PE_FLOATS   8192   // 64 rows * 128 cols (pe, constant)
#define FFB_FLOATS  1024   // 64 rows * 16
#define SMEM_BYTES  ((2 * FSTG_FLOATS + PE_FLOATS + 2 * FFB_FLOATS) * 4)  // 106496

__device__ __forceinline__ uint32_t smem_u32(const void* p)
{
    return (uint32_t)__cvta_generic_to_shared(p);
}
__device__ __forceinline__ void cp16(uint32_t dst, const void* src)
{
    asm volatile("cp.async.cg.shared.global [%0], [%1], 16;" :: "r"(dst), "l"(src));
}
__device__ __forceinline__ unsigned long long pack2(float a, float b)
{
    unsigned long long r;
    asm("mov.b64 %0, {%1, %2};" : "=l"(r) : "f"(a), "f"(b));
    return r;
}
__device__ __forceinline__ void fma2(unsigned long long& d,
                                     unsigned long long a, unsigned long long b)
{
    asm("fma.rn.f32x2 %0, %1, %2, %0;" : "+l"(d) : "l"(a), "l"(b));
}

__global__ __launch_bounds__(TPB, 2) void obs_embed_kernel(
    const float* __restrict__ features,   // [B,64,16]
    const float* __restrict__ W,          // [128,16]
    const float* __restrict__ bias,       // [128]
    const int*   __restrict__ positions,  // [64]
    const __grid_constant__ CUtensorMap mapF,   // feature half (cols 0..127)
    const __grid_constant__ CUtensorMap mapP,   // pe half     (cols 128..255)
    int nUnits)                           // B
{
    extern __shared__ float smem[];
    float* fstg0 = smem;                        // [64][128] feature staging 0
    float* fstg1 = smem + FSTG_FLOATS;          // buffer 1
    float* pes   = smem + 2 * FSTG_FLOATS;      // [64][128] constant pe tile
    float* ffb   = smem + 2 * FSTG_FLOATS + PE_FLOATS;  // [2][64][16]

    const int tid  = threadIdx.x;
    const int lane = tid & 31;
    const int warp = tid >> 5;

    int u = blockIdx.x;

    // Prologue FIRST: prefetch unit u features (4KB; warp w owns rows
    // 8w..8w+7 = 512B = 32 lanes x 16B). Overlaps pe compute below.
    if (u < nUnits)
        cp16(smem_u32(ffb + warp * 128 + lane * 4),
             features + (size_t)u * 1024 + warp * 128 + lane * 4);
    asm volatile("cp.async.commit_group;");

    // Constant pe tile for ALL 64 t's, written once. All-float math
    // (proven rel_err 1.1e-6): exp2f (MUFU) + sincosf.
    for (int idx = tid; idx < 64 * 64; idx += TPB) {
        int r = idx >> 6, j = idx & 63;
        float pos  = (float)__ldg(positions + r);
        float invf = exp2f((float)j * (-13.287712379549449f / 32.0f));
        float s, c;
        sincosf(pos * invf, &s, &c);
        pes[r * DH + 2 * j]     = s;
        pes[r * DH + 2 * j + 1] = c;
    }

    // W into packed registers. Lane owns output cols d = 4*lane + {0..3}.
    unsigned long long wp0[16], wp1[16];
    {
        const float4* Wv = reinterpret_cast<const float4*>(W);
        #pragma unroll
        for (int q = 0; q < 4; ++q) {
            float4 w0 = __ldg(Wv + (4 * lane + 0) * 4 + q);
            float4 w1 = __ldg(Wv + (4 * lane + 1) * 4 + q);
            float4 w2 = __ldg(Wv + (4 * lane + 2) * 4 + q);
            float4 w3 = __ldg(Wv + (4 * lane + 3) * 4 + q);
            wp0[4*q+0] = pack2(w0.x, w1.x);  wp1[4*q+0] = pack2(w2.x, w3.x);
            wp0[4*q+1] = pack2(w0.y, w1.y);  wp1[4*q+1] = pack2(w2.y, w3.y);
            wp0[4*q+2] = pack2(w0.z, w1.z);  wp1[4*q+2] = pack2(w2.z, w3.z);
            wp0[4*q+3] = pack2(w0.w, w1.w);  wp1[4*q+3] = pack2(w2.w, w3.w);
        }
    }
    const unsigned long long bp0 = pack2(__ldg(bias + 4 * lane + 0),
                                         __ldg(bias + 4 * lane + 1));
    const unsigned long long bp1 = pack2(__ldg(bias + 4 * lane + 2),
                                         __ldg(bias + 4 * lane + 3));

    int p = 0;
    for (; u < nUnits; u += GRID, p ^= 1) {
        // Prefetch next unit's features into the other buffer.
        {
            int un = u + GRID;
            if (un < nUnits)
                cp16(smem_u32(ffb + (p ^ 1) * FFB_FLOATS + warp * 128 + lane * 4),
                     features + (size_t)un * 1024 + warp * 128 + lane * 4);
            asm volatile("cp.async.commit_group;");
        }

        // Reuse gate: TMA smem-read of fstg[p] (issued 2 iters ago) done.
        if (tid == 0) asm volatile("cp.async.bulk.wait_group.read 1;");
        __syncthreads();

        // Current features (committed last iter / prologue) ready.
        asm volatile("cp.async.wait_group 1;");
        __syncwarp();

        float* stgp = p ? fstg1 : fstg0;
        const float* fcur = ffb + p * FFB_FLOATS + warp * 128;  // warp's 8 rows

        #pragma unroll
        for (int rr = 0; rr < 8; ++rr) {
            const float4* frow = reinterpret_cast<const float4*>(fcur + rr * 16);
            unsigned long long a0 = bp0, a1 = bp1;
            #pragma unroll
            for (int q = 0; q < 4; ++q) {
                const float4 f = frow[q];   // broadcast LDS, conflict-free
                unsigned long long ff;
                ff = pack2(f.x, f.x); fma2(a0, ff, wp0[4*q+0]); fma2(a1, ff, wp1[4*q+0]);
                ff = pack2(f.y, f.y); fma2(a0, ff, wp0[4*q+1]); fma2(a1, ff, wp1[4*q+1]);
                ff = pack2(f.z, f.z); fma2(a0, ff, wp0[4*q+2]); fma2(a1, ff, wp1[4*q+2]);
                ff = pack2(f.w, f.w); fma2(a0, ff, wp0[4*q+3]); fma2(a1, ff, wp1[4*q+3]);
            }
            uint32_t sa = smem_u32(stgp + (warp * 8 + rr) * DH + lane * 4);
            asm volatile("st.shared.v2.u64 [%0], {%1, %2};"
                         :: "r"(sa), "l"(a0), "l"(a1));
        }
        __syncthreads();

        if (tid == 0) {
            const int row0 = u * 64;
            asm volatile("fence.proxy.async.shared::cta;");
            asm volatile(
                "cp.async.bulk.tensor.2d.global.shared::cta.tile.bulk_group "
                "[%0, {%1, %2}], [%3];"
                :: "l"(&mapF), "r"(0), "r"(row0), "r"(smem_u32(stgp)) : "memory");
            asm volatile(
                "cp.async.bulk.tensor.2d.global.shared::cta.tile.bulk_group "
                "[%0, {%1, %2}], [%3];"
                :: "l"(&mapP), "r"(0), "r"(row0), "r"(smem_u32(pes)) : "memory");
            asm volatile("cp.async.bulk.commit_group;");
        }
    }
    // Drain outstanding bulk stores before CTA exit (smem must stay live).
    asm volatile("cp.async.bulk.wait_group 0;");
    __syncthreads();
}

extern "C" void kernel_launch(void* const* d_in, const int* in_sizes, int n_in,
                              void* d_out, int out_size)
{
    const float* features  = (const float*)d_in[0];
    const float* W         = (const float*)d_in[1];
    const float* bias      = (const float*)d_in[2];
    const int*   positions = (const int*)d_in[3];
    float* out = (float*)d_out;

    const int B = in_sizes[0] / (T_DIM * F_DIM);
    const unsigned long long nRows = (unsigned long long)B * T_DIM;

    typedef CUresult (*EncodeFn)(
        CUtensorMap*, CUtensorMapDataType, cuuint32_t, void*,
        const cuuint64_t*, const cuuint64_t*, const cuuint32_t*,
        const cuuint32_t*, CUtensorMapInterleave, CUtensorMapSwizzle,
        CUtensorMapL2promotion, CUtensorMapFloatOOBfill);
    EncodeFn encode = nullptr;
    cudaDriverEntryPointQueryResult qres;
    cudaGetDriverEntryPoint("cuTensorMapEncodeTiled", (void**)&encode,
                            cudaEnableDefault, &qres);

    // Output viewed as [nRows, 256] f32, pitch 1024B. Two column tiles:
    // cols [0,128) (feature half) and [128,256) (pe half). Box [128, 64].
    cuuint64_t dims[2]    = {128, nRows};
    cuuint64_t strides[1] = {1024};
    cuuint32_t box[2]     = {128, 64};
    cuuint32_t estr[2]    = {1, 1};

    CUtensorMap mapF, mapP;
    encode(&mapF, CU_TENSOR_MAP_DATA_TYPE_FLOAT32, 2, (void*)out,
           dims, strides, box, estr,
           CU_TENSOR_MAP_INTERLEAVE_NONE, CU_TENSOR_MAP_SWIZZLE_NONE,
           CU_TENSOR_MAP_L2_PROMOTION_L2_128B, CU_TENSOR_MAP_FLOAT_OOB_FILL_NONE);
    encode(&mapP, CU_TENSOR_MAP_DATA_TYPE_FLOAT32, 2, (void*)(out + DH),
           dims, strides, box, estr,
           CU_TENSOR_MAP_INTERLEAVE_NONE, CU_TENSOR_MAP_SWIZZLE_NONE,
           CU_TENSOR_MAP_L2_PROMOTION_L2_128B, CU_TENSOR_MAP_FLOAT_OOB_FILL_NONE);

    cudaFuncSetAttribute(obs_embed_kernel,
                         cudaFuncAttributeMaxDynamicSharedMemorySize, SMEM_BYTES);

    obs_embed_kernel<<<GRID, TPB, SMEM_BYTES>>>(features, W, bias, positions,
                                                mapF, mapP, B);
}